// round 6
// baseline (speedup 1.0000x reference)
#include <cuda_runtime.h>
#include <cuda_fp16.h>

typedef unsigned long long ull;

#define PW    768      // padded width/height
#define PAD   128      // border
#define IMGW  512
#define MAGIC 8388608.0f      // 2^23
#define MAGICH 8388607.5f     // 2^23 - 0.5

// fp16 differential quad images, 4x4 BLOCK-TILED:
//   element index E(r,c) = (r>>2)*(PW*4) + c*4 + (r&3)
//   -> one 128B cache line = 4 cols x 4 rows of 8B texels.
// Texel = (v00, dx | dy, dxy); bilinear: val = (v00 + wr*dy) + wc*(dx + wr*dxy)
// A (normal):     rows = image y, cols = image x (padded space)
// B (transposed): rows = image x, cols = image y
__device__ ull g_quadA[PW * PW];
__device__ ull g_quadB[PW * PW];

__device__ __forceinline__ int tile_idx(int r, int c) {
    return (r >> 2) * (PW * 4) + (c << 2) + (r & 3);
}

// ---------------- packed f32x2 helpers ----------------
__device__ __forceinline__ ull f2u(float a, float b) {
    ull r; asm("mov.b64 %0, {%1, %2};" : "=l"(r) : "f"(a), "f"(b)); return r;
}
__device__ __forceinline__ void u2f(ull v, float& a, float& b) {
    asm("mov.b64 {%0, %1}, %2;" : "=f"(a), "=f"(b) : "l"(v));
}
__device__ __forceinline__ ull fma2(ull a, ull b, ull c) {
    ull d; asm("fma.rn.f32x2 %0, %1, %2, %3;" : "=l"(d) : "l"(a), "l"(b), "l"(c)); return d;
}
__device__ __forceinline__ ull add2(ull a, ull b) {
    ull d; asm("add.rn.f32x2 %0, %1, %2;" : "=l"(d) : "l"(a), "l"(b)); return d;
}
__device__ __forceinline__ ull packq(float v00, float v01, float v10, float v11) {
    float dx  = v01 - v00;
    float dy  = v10 - v00;
    float dxy = (v11 - v10) - (v01 - v00);
    __half2 lo = __floats2half2_rn(v00, dx);
    __half2 hi = __floats2half2_rn(dy, dxy);
    unsigned a = *reinterpret_cast<unsigned*>(&lo);
    unsigned b = *reinterpret_cast<unsigned*>(&hi);
    return (ull)a | ((ull)b << 32);
}

__device__ __forceinline__ float ipad(const float* img, int v, int u) {
    int sv = v - PAD, su = u - PAD;
    if (sv < 0 || sv >= IMGW || su < 0 || su >= IMGW) return 0.0f;
    return __ldg(&img[sv * IMGW + su]);
}

// ---------------- fused prep: both differential quad images (tiled) ----------------
__global__ void prep_kernel(const float* __restrict__ img) {
    __shared__ float S[33][34];            // S[j][i] = Ip(r0+j, c0+i)
    const int r0 = blockIdx.x * 32;
    const int c0 = blockIdx.y * 32;
    const int tx = threadIdx.x;            // 0..31
    const int ty = threadIdx.y;            // 0..7

    for (int j = ty; j < 33; j += 8)
        for (int i = tx; i < 33; i += 32)
            S[j][i] = ipad(img, r0 + j, c0 + i);
    __syncthreads();

    for (int j = ty; j < 32; j += 8) {
        // QA rows = image y
        g_quadA[tile_idx(r0 + j, c0 + tx)] =
            packq(S[j][tx], S[j][tx + 1], S[j + 1][tx], S[j + 1][tx + 1]);
        // QB rows = image x (transposed); col+1 -> image y+1, row+1 -> image x+1
        g_quadB[tile_idx(c0 + j, r0 + tx)] =
            packq(S[tx][j], S[tx + 1][j], S[tx][j + 1], S[tx + 1][j + 1]);
    }
}

// ---------------- main radon kernel ----------------
// Warp = 8 detectors x 4 y-lanes. Thread: 4 streams x 32 samples, y = yi + 4*t + 128*k.
__global__ void __launch_bounds__(128) radon_kernel(const float* __restrict__ angles,
                                                    float* __restrict__ out) {
    const int lane = threadIdx.x & 31;
    const int warp = threadIdx.x >> 5;
    const int xi   = lane & 7;
    const int yi   = lane >> 3;
    const int x    = blockIdx.x * 32 + warp * 8 + xi;
    const int a    = blockIdx.y;

    float s, c;
    sincosf(__ldg(&angles[a]), &s, &c);

    const float bx = fmaf((float)x, 2.0f / 512.0f, 1.0f / 512.0f - 1.0f);
    const float Cx = fmaf(256.0f * c, bx, 383.5f - 255.5f * s);
    const float Cy = fmaf(-256.0f * s, bx, 383.5f - 255.5f * c);

    // layout selection: row dim gets the small per-detector delta
    const bool  tr   = fabsf(s) > fabsf(c);
    const float dcol = tr ? c : s;        // per-y col step (small per detector usage)
    const float drow = tr ? s : c;
    const float Ca   = tr ? Cy : Cx;
    const float Cb   = tr ? Cx : Cy;

    // de-bias for magic ints: Ri = 0x4B000000 + r, Ci = 0x4B000000 + c
    // byte offset used: (Ri>>2)*(PW*4*8) + Ci*32 + (Ri&3)*8
    const long long BIAS = (long long)(0x4B000000 >> 2) * (PW * 4 * 8)
                         + ((long long)0x4B000000 << 5);
    const char* basep = (const char*)(tr ? g_quadB : g_quadA) - BIAS;

    const ull S4    = f2u(4.0f * dcol, 4.0f * drow);
    const ull NEG1  = f2u(-1.0f, -1.0f);
    const ull ONE2  = f2u(1.0f, 1.0f);
    const ull MAGH2 = f2u(MAGICH, MAGICH);    // rn(P + (2^23-0.5)) = MAGIC + floor(P)
    const ull NMAG2 = f2u(-MAGIC, -MAGIC);

    const float y0 = (float)yi;
    ull C0 = f2u(fmaf(y0 +   0.0f, dcol, Ca), fmaf(y0 +   0.0f, drow, Cb));
    ull C1 = f2u(fmaf(y0 + 128.0f, dcol, Ca), fmaf(y0 + 128.0f, drow, Cb));
    ull C2 = f2u(fmaf(y0 + 256.0f, dcol, Ca), fmaf(y0 + 256.0f, drow, Cb));
    ull C3 = f2u(fmaf(y0 + 384.0f, dcol, Ca), fmaf(y0 + 384.0f, drow, Cb));

    float am0 = 0.0f, am1 = 0.0f, am2 = 0.0f, am3 = 0.0f;
    float ad0 = 0.0f, ad1 = 0.0f, ad2 = 0.0f, ad3 = 0.0f;

    ull t2 = f2u(0.0f, 0.0f);

    #pragma unroll 2
    for (int i = 0; i < 32; i++) {
        #pragma unroll
        for (int k = 0; k < 4; k++) {
            const ull Ck = (k == 0) ? C0 : (k == 1) ? C1 : (k == 2) ? C2 : C3;
            float& am    = (k == 0) ? am0 : (k == 1) ? am1 : (k == 2) ? am2 : am3;
            float& ad    = (k == 0) ? ad0 : (k == 1) ? ad1 : (k == 2) ? ad2 : ad3;

            // packed coords (col, row)
            ull p = fma2(t2, S4, Ck);
            ull t = add2(p, MAGH2);            // MAGIC + floor(col|row)
            ull f = add2(t, NMAG2);            // exact floors as floats
            ull w = fma2(f, NEG1, p);          // fractional weights (wc, wr)

            float tcf, trf; u2f(t, tcf, trf);
            int Ci = __float_as_int(tcf);
            int Ri = __float_as_int(trf);
            const char* ap = basep
                           + (long long)(Ri >> 2) * (PW * 4 * 8)
                           + ((long long)Ci << 5)
                           + ((Ri & 3) << 3);
            uint2 q = __ldg(reinterpret_cast<const uint2*>(ap));
            __half2 A = *reinterpret_cast<__half2*>(&q.x);   // (v00, dx)
            __half2 B = *reinterpret_cast<__half2*>(&q.y);   // (dy, dxy)

            float wc, wr; u2f(w, wc, wr);
            unsigned wr2u;
            asm("cvt.rn.f16x2.f32 %0, %1, %2;" : "=r"(wr2u) : "f"(wr), "f"(wr));
            __half2 wr2 = *reinterpret_cast<__half2*>(&wr2u);

            __half2 mh = __hfma2(wr2, B, A);                 // (m0, md)
            float m0 = __low2float(mh), md = __high2float(mh);

            am += m0;
            ad = fmaf(wc, md, ad);
        }
        t2 = add2(t2, ONE2);
    }

    float v = ((am0 + ad0) + (am1 + ad1)) + ((am2 + ad2) + (am3 + ad3));
    v += __shfl_xor_sync(0xFFFFFFFFu, v, 8);
    v += __shfl_xor_sync(0xFFFFFFFFu, v, 16);
    if (yi == 0)
        out[a * IMGW + x] = v;
}

extern "C" void kernel_launch(void* const* d_in, const int* in_sizes, int n_in,
                              void* d_out, int out_size) {
    const float* data   = (const float*)d_in[0];
    const float* angles = (const float*)d_in[1];
    if (n_in >= 2 && in_sizes[0] < in_sizes[1]) {
        const float* t = data; data = angles; angles = t;
    }
    int nA = (in_sizes[0] < in_sizes[1]) ? in_sizes[0] : in_sizes[1];

    float* out = (float*)d_out;

    dim3 pgrid(PW / 32, PW / 32);
    prep_kernel<<<pgrid, dim3(32, 8)>>>(data);

    dim3 rgrid(IMGW / 32, nA);
    radon_kernel<<<rgrid, 128>>>(angles, out);
}

// round 7
// speedup vs baseline: 1.1831x; 1.1831x over previous
#include <cuda_runtime.h>
#include <cuda_fp16.h>

typedef unsigned long long ull;

#define PW    768      // padded width/height
#define PAD   128      // border
#define IMGW  512
#define MAGIC 8388608.0f      // 2^23
#define MAGICH 8388607.5f     // 2^23 - 0.5

// fp16 differential quad images, 4x4 BLOCK-TILED:
//   element E(r,c) = (r>>2)*(PW*4) + (c<<2) + (r&3)
//   -> one 128B cache line = 4 cols x 4 rows of 8B texels.
// Texel = (v00, dx | dy, dxy); bilinear: val = (v00 + wr*dy) + wc*(dx + wr*dxy)
// A (normal):     rows = image y, cols = image x (padded space)
// B (transposed): rows = image x, cols = image y
__device__ ull g_quadA[PW * PW];
__device__ ull g_quadB[PW * PW];

__device__ __forceinline__ int tile_idx(int r, int c) {
    return (r >> 2) * (PW * 4) + (c << 2) + (r & 3);
}

// ---------------- packed f32x2 helpers ----------------
__device__ __forceinline__ ull f2u(float a, float b) {
    ull r; asm("mov.b64 %0, {%1, %2};" : "=l"(r) : "f"(a), "f"(b)); return r;
}
__device__ __forceinline__ void u2f(ull v, float& a, float& b) {
    asm("mov.b64 {%0, %1}, %2;" : "=f"(a), "=f"(b) : "l"(v));
}
__device__ __forceinline__ ull fma2(ull a, ull b, ull c) {
    ull d; asm("fma.rn.f32x2 %0, %1, %2, %3;" : "=l"(d) : "l"(a), "l"(b), "l"(c)); return d;
}
__device__ __forceinline__ ull add2(ull a, ull b) {
    ull d; asm("add.rn.f32x2 %0, %1, %2;" : "=l"(d) : "l"(a), "l"(b)); return d;
}
__device__ __forceinline__ ull packq(float v00, float v01, float v10, float v11) {
    float dx  = v01 - v00;
    float dy  = v10 - v00;
    float dxy = (v11 - v10) - (v01 - v00);
    __half2 lo = __floats2half2_rn(v00, dx);
    __half2 hi = __floats2half2_rn(dy, dxy);
    unsigned a = *reinterpret_cast<unsigned*>(&lo);
    unsigned b = *reinterpret_cast<unsigned*>(&hi);
    return (ull)a | ((ull)b << 32);
}

__device__ __forceinline__ float ipad(const float* img, int v, int u) {
    int sv = v - PAD, su = u - PAD;
    if (sv < 0 || sv >= IMGW || su < 0 || su >= IMGW) return 0.0f;
    return __ldg(&img[sv * IMGW + su]);
}

// ---------------- fused prep: both differential quad images (tiled) ----------------
__global__ void prep_kernel(const float* __restrict__ img) {
    __shared__ float S[33][34];            // S[j][i] = Ip(r0+j, c0+i)
    const int r0 = blockIdx.x * 32;
    const int c0 = blockIdx.y * 32;
    const int tx = threadIdx.x;            // 0..31
    const int ty = threadIdx.y;            // 0..7

    for (int j = ty; j < 33; j += 8)
        for (int i = tx; i < 33; i += 32)
            S[j][i] = ipad(img, r0 + j, c0 + i);
    __syncthreads();

    for (int j = ty; j < 32; j += 8) {
        // QA rows = image y
        g_quadA[tile_idx(r0 + j, c0 + tx)] =
            packq(S[j][tx], S[j][tx + 1], S[j + 1][tx], S[j + 1][tx + 1]);
        // QB rows = image x (transposed)
        g_quadB[tile_idx(c0 + j, r0 + tx)] =
            packq(S[tx][j], S[tx + 1][j], S[tx][j + 1], S[tx + 1][j + 1]);
    }
}

// ---------------- main radon kernel ----------------
// Warp = 8 detectors x 4 y-lanes. Thread: 4 streams x 32 samples, y = yi + 4*t + 128*k.
__global__ void __launch_bounds__(128, 12) radon_kernel(const float* __restrict__ angles,
                                                        float* __restrict__ out) {
    const int lane = threadIdx.x & 31;
    const int warp = threadIdx.x >> 5;
    const int xi   = lane & 7;
    const int yi   = lane >> 3;
    const int x    = blockIdx.x * 32 + warp * 8 + xi;
    const int a    = blockIdx.y;

    float s, c;
    sincosf(__ldg(&angles[a]), &s, &c);

    const float bx = fmaf((float)x, 2.0f / 512.0f, 1.0f / 512.0f - 1.0f);
    const float Cx = fmaf(256.0f * c, bx, 383.5f - 255.5f * s);
    const float Cy = fmaf(-256.0f * s, bx, 383.5f - 255.5f * c);

    // layout selection
    const bool  tr   = fabsf(s) > fabsf(c);
    const float dcol = tr ? c : s;
    const float drow = tr ? s : c;
    const float Ca   = tr ? Cy : Cx;
    const float Cb   = tr ? Cx : Cy;

    // Biased magic-int addressing with the identity
    //   (r>>2)*24576 + (r&3)*8 == r*8 + (r>>2)*24544
    // Ri = B + r, Ci = B + c with B = 0x4B000000 (B%4 == 0, so shifts/adds split exactly).
    // lo = Ri*8 + Ci*32 computed in wrapping u32: true value B*40 + r*8 + c*32,
    //   B*40 = 11*2^32 + 3087007744 and r*8+c*32 <= 30720, so the wrap is the
    //   CONSTANT 11*2^32 -> fold (B>>2)*24544 + (B*40 mod 2^32) into basep.
    const char* basep = (const char*)(tr ? g_quadB : g_quadA)
                      - (ull)(0x4B000000u >> 2) * 24544ull
                      - ((0x4B000000ull * 40ull) & 0xFFFFFFFFull);

    const ull S4    = f2u(4.0f * dcol, 4.0f * drow);
    const ull NEG1  = f2u(-1.0f, -1.0f);
    const ull ONE2  = f2u(1.0f, 1.0f);
    const ull MAGH2 = f2u(MAGICH, MAGICH);    // rn(P + (2^23-0.5)) = MAGIC + floor(P)
    const ull NMAG2 = f2u(-MAGIC, -MAGIC);

    const float y0 = (float)yi;
    ull C0 = f2u(fmaf(y0 +   0.0f, dcol, Ca), fmaf(y0 +   0.0f, drow, Cb));
    ull C1 = f2u(fmaf(y0 + 128.0f, dcol, Ca), fmaf(y0 + 128.0f, drow, Cb));
    ull C2 = f2u(fmaf(y0 + 256.0f, dcol, Ca), fmaf(y0 + 256.0f, drow, Cb));
    ull C3 = f2u(fmaf(y0 + 384.0f, dcol, Ca), fmaf(y0 + 384.0f, drow, Cb));

    float acc0 = 0.0f, acc1 = 0.0f, acc2 = 0.0f, acc3 = 0.0f;

    ull t2 = f2u(0.0f, 0.0f);

    #pragma unroll 2
    for (int i = 0; i < 32; i++) {
        #pragma unroll
        for (int k = 0; k < 4; k++) {
            const ull Ck = (k == 0) ? C0 : (k == 1) ? C1 : (k == 2) ? C2 : C3;
            float& acc   = (k == 0) ? acc0 : (k == 1) ? acc1 : (k == 2) ? acc2 : acc3;

            // packed coords (col, row), exact from base (no drift)
            ull p = fma2(t2, S4, Ck);
            ull t = add2(p, MAGH2);            // MAGIC + floor(col|row)
            ull f = add2(t, NMAG2);            // exact floors as floats
            ull w = fma2(f, NEG1, p);          // fractional weights (wc, wr)

            float tcf, trf; u2f(t, tcf, trf);
            int Ci = __float_as_int(tcf);
            int Ri = __float_as_int(trf);
            unsigned lo = (unsigned)Ri * 8u + (unsigned)Ci * 32u;   // wrapping, constant-folded
            const char* ap = basep + (long long)(Ri >> 2) * 24544 + lo;

            uint2 q = __ldg(reinterpret_cast<const uint2*>(ap));
            __half2 A = *reinterpret_cast<__half2*>(&q.x);   // (v00, dx)
            __half2 B = *reinterpret_cast<__half2*>(&q.y);   // (dy, dxy)

            float wc, wr; u2f(w, wc, wr);
            unsigned wr2u;
            asm("cvt.rn.f16x2.f32 %0, %1, %2;" : "=r"(wr2u) : "f"(wr), "f"(wr));
            __half2 wr2 = *reinterpret_cast<__half2*>(&wr2u);

            __half2 mh = __hfma2(wr2, B, A);                 // (m0, md)
            float m0 = __low2float(mh), md = __high2float(mh);

            acc += m0;
            acc = fmaf(wc, md, acc);
        }
        t2 = add2(t2, ONE2);
    }

    float v = (acc0 + acc1) + (acc2 + acc3);
    v += __shfl_xor_sync(0xFFFFFFFFu, v, 8);
    v += __shfl_xor_sync(0xFFFFFFFFu, v, 16);
    if (yi == 0)
        out[a * IMGW + x] = v;
}

extern "C" void kernel_launch(void* const* d_in, const int* in_sizes, int n_in,
                              void* d_out, int out_size) {
    const float* data   = (const float*)d_in[0];
    const float* angles = (const float*)d_in[1];
    if (n_in >= 2 && in_sizes[0] < in_sizes[1]) {
        const float* t = data; data = angles; angles = t;
    }
    int nA = (in_sizes[0] < in_sizes[1]) ? in_sizes[0] : in_sizes[1];

    float* out = (float*)d_out;

    dim3 pgrid(PW / 32, PW / 32);
    prep_kernel<<<pgrid, dim3(32, 8)>>>(data);

    dim3 rgrid(IMGW / 32, nA);
    radon_kernel<<<rgrid, 128>>>(angles, out);
}